// round 3
// baseline (speedup 1.0000x reference)
#include <cuda_runtime.h>
#include <cuda_bf16.h>

#define N_NODES 20000
#define M_EDGES 5000
#define D_IN    256
#define D_OUT   512
#define NNZ_MAX 6000000
#define EPS     1e-5f

// ---------------- scratch (static device allocations; no cudaMalloc) -------
__device__ int   g_deg_e[M_EDGES];
__device__ int   g_deg_v[N_NODES];
__device__ int   g_off_e[M_EDGES + 1];
__device__ int   g_off_v[N_NODES + 1];
__device__ int   g_cur_e[M_EDGES];
__device__ int   g_cur_v[N_NODES];
__device__ float g_inv_de[M_EDGES];
__device__ float g_inv_dv[N_NODES];
__device__ int   g_csc[NNZ_MAX];   // per-edge node lists
__device__ int   g_csr[NNZ_MAX];   // per-node edge lists
__device__ __nv_bfloat16 g_xproj[(size_t)N_NODES * D_OUT]; // x @ W_node (bf16)
__device__ __nv_bfloat16 g_efeat[(size_t)M_EDGES * D_OUT]; // edge features (bf16)

// ---------------- K0: zero counters ----------------------------------------
__global__ void init_kernel() {
    int i = blockIdx.x * blockDim.x + threadIdx.x;
    int stride = gridDim.x * blockDim.x;
    for (int j = i; j < M_EDGES; j += stride) { g_deg_e[j] = 0; g_cur_e[j] = 0; }
    for (int j = i; j < N_NODES; j += stride) { g_deg_v[j] = 0; g_cur_v[j] = 0; }
}

// ---------------- K1: degrees (one pass over H) -----------------------------
// Each block processes whole rows; per-column counts accumulate in smem
// (thread-private column ownership: the same thread owns the same columns
// every row, so increments are race-free). Row degree via warp reduction.
__global__ void degree_kernel(const float* __restrict__ H) {
    __shared__ int s_col[M_EDGES];   // 20 KB
    __shared__ int s_row;
    for (int c = threadIdx.x; c < M_EDGES; c += blockDim.x) s_col[c] = 0;
    __syncthreads();

    for (int v = blockIdx.x; v < N_NODES; v += gridDim.x) {
        if (threadIdx.x == 0) s_row = 0;
        __syncthreads();
        const float4* row = (const float4*)(H + (size_t)v * M_EDGES);
        int cnt = 0;
        for (int c4 = threadIdx.x; c4 < M_EDGES / 4; c4 += blockDim.x) {
            float4 h = row[c4];
            int b = c4 * 4;
            if (h.x != 0.f) { cnt++; s_col[b + 0]++; }
            if (h.y != 0.f) { cnt++; s_col[b + 1]++; }
            if (h.z != 0.f) { cnt++; s_col[b + 2]++; }
            if (h.w != 0.f) { cnt++; s_col[b + 3]++; }
        }
        #pragma unroll
        for (int o = 16; o > 0; o >>= 1) cnt += __shfl_xor_sync(0xffffffffu, cnt, o);
        if ((threadIdx.x & 31) == 0) atomicAdd(&s_row, cnt);
        __syncthreads();
        if (threadIdx.x == 0) g_deg_v[v] = s_row;
        __syncthreads();
    }
    for (int c = threadIdx.x; c < M_EDGES; c += blockDim.x)
        if (s_col[c]) atomicAdd(&g_deg_e[c], s_col[c]);
}

// ---------------- K2: exclusive scans + clamped inverse degrees -------------
__global__ void scan_kernel() {
    __shared__ int part[1025];
    int t = threadIdx.x, T = blockDim.x;

    // edges
    {
        const int n = M_EDGES;
        int chunk = (n + T - 1) / T;
        int lo = min(n, t * chunk), hi = min(n, lo + chunk);
        int s = 0;
        for (int i = lo; i < hi; i++) s += g_deg_e[i];
        part[t] = s; __syncthreads();
        if (t == 0) {
            int run = 0;
            for (int i = 0; i < T; i++) { int vv = part[i]; part[i] = run; run += vv; }
            part[T] = run;
        }
        __syncthreads();
        int run = part[t];
        for (int i = lo; i < hi; i++) {
            g_off_e[i] = run;
            int d = g_deg_e[i]; run += d;
            g_inv_de[i] = 1.0f / (float)(d > 1 ? d : 1);
        }
        if (t == 0) g_off_e[n] = part[T];
        __syncthreads();
    }
    // nodes
    {
        const int n = N_NODES;
        int chunk = (n + T - 1) / T;
        int lo = min(n, t * chunk), hi = min(n, lo + chunk);
        int s = 0;
        for (int i = lo; i < hi; i++) s += g_deg_v[i];
        part[t] = s; __syncthreads();
        if (t == 0) {
            int run = 0;
            for (int i = 0; i < T; i++) { int vv = part[i]; part[i] = run; run += vv; }
            part[T] = run;
        }
        __syncthreads();
        int run = part[t];
        for (int i = lo; i < hi; i++) {
            g_off_v[i] = run;
            int d = g_deg_v[i]; run += d;
            g_inv_dv[i] = 1.0f / (float)(d > 1 ? d : 1);
        }
        if (t == 0) g_off_v[n] = part[T];
    }
}

// ---------------- K3: fill CSR/CSC (second pass over H) ---------------------
__global__ void fill_kernel(const float* __restrict__ H) {
    for (int v = blockIdx.x; v < N_NODES; v += gridDim.x) {
        const float4* row = (const float4*)(H + (size_t)v * M_EDGES);
        int obase_v = g_off_v[v];
        for (int c4 = threadIdx.x; c4 < M_EDGES / 4; c4 += blockDim.x) {
            float4 h = row[c4];
            int b = c4 * 4;
            #define HANDLE(val, e_)                                              \
                if ((val) != 0.f) {                                              \
                    int e = (e_);                                                \
                    int p = atomicAdd(&g_cur_e[e], 1);                           \
                    g_csc[g_off_e[e] + p] = v;                                   \
                    int q = atomicAdd(&g_cur_v[v], 1);                           \
                    g_csr[obase_v + q] = e;                                      \
                }
            HANDLE(h.x, b + 0)
            HANDLE(h.y, b + 1)
            HANDLE(h.z, b + 2)
            HANDLE(h.w, b + 3)
            #undef HANDLE
        }
    }
}

// ---------------- K4: fp32 projection GEMM ----------------------------------
// C = x @ W, 64x64x32 tiling, 256 threads, 4x4 microtile.
// grid.y tiles 0..7  -> x@W_node  -> g_xproj (bf16)
// grid.y tiles 8..15 -> x@W_res   -> d_out   (fp32 residual, pre-LN)
#define BM 64
#define BN 64
#define BK 32
__global__ void proj_gemm(const float* __restrict__ A,
                          const float* __restrict__ Wn,
                          const float* __restrict__ Wr,
                          float* __restrict__ dres) {
    __shared__ float As[BK][BM + 1];
    __shared__ float Bs[BK][BN];

    int tb_m = blockIdx.x * BM;
    int n0 = blockIdx.y * BN;
    const float* B = (n0 < D_OUT) ? Wn : Wr;
    int bcol = n0 & (D_OUT - 1);

    int tid = threadIdx.x;
    int tx = tid % 16, ty = tid / 16;
    int a_k4 = (tid % 8) * 4, a_r = tid / 8;   // A: 32 rows x (8x4) k per pass
    int b_c4 = (tid % 16) * 4, b_r = tid / 16; // B: 16 rows x (16x4) n per pass

    float acc[4][4];
    #pragma unroll
    for (int i = 0; i < 4; i++)
        #pragma unroll
        for (int j = 0; j < 4; j++) acc[i][j] = 0.f;

    for (int k0 = 0; k0 < D_IN; k0 += BK) {
        #pragma unroll
        for (int rr = 0; rr < 2; rr++) {
            int m = tb_m + a_r + rr * 32;
            float4 av = (m < N_NODES)
                ? *(const float4*)(A + (size_t)m * D_IN + k0 + a_k4)
                : make_float4(0.f, 0.f, 0.f, 0.f);
            As[a_k4 + 0][a_r + rr * 32] = av.x;
            As[a_k4 + 1][a_r + rr * 32] = av.y;
            As[a_k4 + 2][a_r + rr * 32] = av.z;
            As[a_k4 + 3][a_r + rr * 32] = av.w;
        }
        #pragma unroll
        for (int rr = 0; rr < 2; rr++) {
            int k = k0 + b_r + rr * 16;
            float4 bv = *(const float4*)(B + (size_t)k * D_OUT + bcol + b_c4);
            *(float4*)&Bs[b_r + rr * 16][b_c4] = bv;
        }
        __syncthreads();
        #pragma unroll
        for (int kk = 0; kk < BK; kk++) {
            float a[4], b[4];
            #pragma unroll
            for (int i = 0; i < 4; i++) a[i] = As[kk][ty * 4 + i];
            #pragma unroll
            for (int j = 0; j < 4; j++) b[j] = Bs[kk][tx * 4 + j];
            #pragma unroll
            for (int i = 0; i < 4; i++)
                #pragma unroll
                for (int j = 0; j < 4; j++) acc[i][j] += a[i] * b[j];
        }
        __syncthreads();
    }

    if (n0 < D_OUT) {
        #pragma unroll
        for (int i = 0; i < 4; i++) {
            int m = tb_m + ty * 4 + i;
            if (m < N_NODES) {
                __nv_bfloat162 p0 = __floats2bfloat162_rn(acc[i][0], acc[i][1]);
                __nv_bfloat162 p1 = __floats2bfloat162_rn(acc[i][2], acc[i][3]);
                __nv_bfloat162* op =
                    (__nv_bfloat162*)(g_xproj + (size_t)m * D_OUT + n0 + tx * 4);
                op[0] = p0; op[1] = p1;
            }
        }
    } else {
        #pragma unroll
        for (int i = 0; i < 4; i++) {
            int m = tb_m + ty * 4 + i;
            if (m < N_NODES) {
                float4 st = make_float4(acc[i][0], acc[i][1], acc[i][2], acc[i][3]);
                *(float4*)(dres + (size_t)m * D_OUT + bcol + tx * 4) = st;
            }
        }
    }
}

// ---------------- K5: edge aggregation (CSC gather, L2-resident) ------------
// One block per edge, 128 threads x 4 dims (uint2 = 4 bf16).
__global__ void edge_agg_kernel() {
    int e = blockIdx.x;
    int t = threadIdx.x;
    int beg = g_off_e[e];
    int deg = g_off_e[e + 1] - beg;
    float4 acc = make_float4(0.f, 0.f, 0.f, 0.f);
    __shared__ int s_idx[128];

    for (int base = 0; base < deg; base += 128) {
        int cnt = min(128, deg - base);
        if (t < cnt) s_idx[t] = g_csc[beg + base + t];
        __syncthreads();
        int i = 0;
        for (; i + 4 <= cnt; i += 4) {
            #pragma unroll
            for (int u = 0; u < 4; u++) {
                int v = s_idx[i + u];
                uint2 raw = ((const uint2*)(g_xproj + (size_t)v * D_OUT))[t];
                __nv_bfloat162 p0 = *(__nv_bfloat162*)&raw.x;
                __nv_bfloat162 p1 = *(__nv_bfloat162*)&raw.y;
                float2 f0 = __bfloat1622float2(p0);
                float2 f1 = __bfloat1622float2(p1);
                acc.x += f0.x; acc.y += f0.y; acc.z += f1.x; acc.w += f1.y;
            }
        }
        for (; i < cnt; i++) {
            int v = s_idx[i];
            uint2 raw = ((const uint2*)(g_xproj + (size_t)v * D_OUT))[t];
            __nv_bfloat162 p0 = *(__nv_bfloat162*)&raw.x;
            __nv_bfloat162 p1 = *(__nv_bfloat162*)&raw.y;
            float2 f0 = __bfloat1622float2(p0);
            float2 f1 = __bfloat1622float2(p1);
            acc.x += f0.x; acc.y += f0.y; acc.z += f1.x; acc.w += f1.y;
        }
        __syncthreads();
    }

    float inv = g_inv_de[e];
    __nv_bfloat162 o0 = __floats2bfloat162_rn(acc.x * inv, acc.y * inv);
    __nv_bfloat162 o1 = __floats2bfloat162_rn(acc.z * inv, acc.w * inv);
    uint2 out;
    out.x = *(unsigned*)&o0;
    out.y = *(unsigned*)&o1;
    ((uint2*)(g_efeat + (size_t)e * D_OUT))[t] = out;
}

// ---------------- K6: node aggregation + residual + LayerNorm ---------------
// One block per node, 128 threads x 4 dims; residual was pre-stored in d_out.
__global__ void node_agg_kernel(float* __restrict__ out,
                                const float* __restrict__ gamma,
                                const float* __restrict__ beta) {
    int v = blockIdx.x;
    int t = threadIdx.x;
    int beg = g_off_v[v];
    int deg = g_off_v[v + 1] - beg;
    float4 acc = make_float4(0.f, 0.f, 0.f, 0.f);
    __shared__ int s_idx[128];

    for (int base = 0; base < deg; base += 128) {
        int cnt = min(128, deg - base);
        if (t < cnt) s_idx[t] = g_csr[beg + base + t];
        __syncthreads();
        int i = 0;
        for (; i + 4 <= cnt; i += 4) {
            #pragma unroll
            for (int u = 0; u < 4; u++) {
                int e = s_idx[i + u];
                uint2 raw = ((const uint2*)(g_efeat + (size_t)e * D_OUT))[t];
                __nv_bfloat162 p0 = *(__nv_bfloat162*)&raw.x;
                __nv_bfloat162 p1 = *(__nv_bfloat162*)&raw.y;
                float2 f0 = __bfloat1622float2(p0);
                float2 f1 = __bfloat1622float2(p1);
                acc.x += f0.x; acc.y += f0.y; acc.z += f1.x; acc.w += f1.y;
            }
        }
        for (; i < cnt; i++) {
            int e = s_idx[i];
            uint2 raw = ((const uint2*)(g_efeat + (size_t)e * D_OUT))[t];
            __nv_bfloat162 p0 = *(__nv_bfloat162*)&raw.x;
            __nv_bfloat162 p1 = *(__nv_bfloat162*)&raw.y;
            float2 f0 = __bfloat1622float2(p0);
            float2 f1 = __bfloat1622float2(p1);
            acc.x += f0.x; acc.y += f0.y; acc.z += f1.x; acc.w += f1.y;
        }
        __syncthreads();
    }

    float inv = g_inv_dv[v];
    float4 res = ((const float4*)(out + (size_t)v * D_OUT))[t];
    float4 h;
    h.x = acc.x * inv + res.x;
    h.y = acc.y * inv + res.y;
    h.z = acc.z * inv + res.z;
    h.w = acc.w * inv + res.w;

    float s  = h.x + h.y + h.z + h.w;
    float sq = h.x * h.x + h.y * h.y + h.z * h.z + h.w * h.w;
    #pragma unroll
    for (int o = 16; o > 0; o >>= 1) {
        s  += __shfl_xor_sync(0xffffffffu, s, o);
        sq += __shfl_xor_sync(0xffffffffu, sq, o);
    }
    __shared__ float red[8];
    __shared__ float s_mu, s_rstd;
    int warp = t >> 5, lane = t & 31;
    if (lane == 0) { red[warp] = s; red[4 + warp] = sq; }
    __syncthreads();
    if (t == 0) {
        float S = red[0] + red[1] + red[2] + red[3];
        float Q = red[4] + red[5] + red[6] + red[7];
        float mu = S * (1.0f / (float)D_OUT);
        float var = Q * (1.0f / (float)D_OUT) - mu * mu;
        s_mu = mu;
        s_rstd = rsqrtf(var + EPS);
    }
    __syncthreads();
    float mu = s_mu, r = s_rstd;

    float4 g = ((const float4*)gamma)[t];
    float4 b = ((const float4*)beta)[t];
    float4 o;
    o.x = (h.x - mu) * r * g.x + b.x;
    o.y = (h.y - mu) * r * g.y + b.y;
    o.z = (h.z - mu) * r * g.z + b.z;
    o.w = (h.w - mu) * r * g.w + b.w;
    ((float4*)(out + (size_t)v * D_OUT))[t] = o;
}

// ---------------- launch -----------------------------------------------------
extern "C" void kernel_launch(void* const* d_in, const int* in_sizes, int n_in,
                              void* d_out, int out_size) {
    const float* x     = (const float*)d_in[0];
    const float* H     = (const float*)d_in[1];
    const float* Wn    = (const float*)d_in[2];
    const float* Wr    = (const float*)d_in[3];
    const float* gamma = (const float*)d_in[4];
    const float* beta  = (const float*)d_in[5];
    float* out = (float*)d_out;

    init_kernel<<<64, 256>>>();
    degree_kernel<<<1024, 256>>>(H);
    scan_kernel<<<1, 1024>>>();
    fill_kernel<<<2048, 256>>>(H);

    dim3 gg((N_NODES + BM - 1) / BM, (2 * D_OUT) / BN);
    proj_gemm<<<gg, 256>>>(x, Wn, Wr, out);

    edge_agg_kernel<<<M_EDGES, 128>>>();
    node_agg_kernel<<<N_NODES, 128>>>(out, gamma, beta);
}